// round 13
// baseline (speedup 1.0000x reference)
#include <cuda_runtime.h>
#include <math.h>

#define B_SETS 65536
#define P      22
#define INF_   6
#define HID    64
#define OUTD   128

#define WPB     8
#define THREADS (WPB * 32)
#define GRID    592                 // 148 SMs * 4 blocks/SM
#define NWARPS  (GRID * WPB)        // 4736 ; sets/warp = 65536/4736 = 512/37

__device__ __forceinline__ unsigned long long pack2(float lo, float hi) {
    unsigned long long r;
    asm("mov.b64 %0, {%1,%2};" : "=l"(r) : "f"(lo), "f"(hi));
    return r;
}
__device__ __forceinline__ void unpack2(unsigned long long v, float& lo, float& hi) {
    asm("mov.b64 {%0,%1}, %2;" : "=f"(lo), "=f"(hi) : "l"(v));
}
__device__ __forceinline__ unsigned long long fma2(unsigned long long a,
                                                   unsigned long long b,
                                                   unsigned long long c) {
    unsigned long long d;
    asm("fma.rn.f32x2 %0, %1, %2, %3;" : "=l"(d) : "l"(a), "l"(b), "l"(c));
    return d;
}

// fast atan2: minimax deg-11 odd poly on [0,1], abs err ~1e-6 (output tol 1e-3)
__device__ __forceinline__ float fast_atan2(float y, float x) {
    const float ax = fabsf(x), ay = fabsf(y);
    const float mx = fmaxf(ax, ay), mn = fminf(ax, ay);
    float t = (mx > 0.f) ? __fdividef(mn, mx) : 0.f;
    const float a = t * t;
    float p = fmaf(a, -0.01172120f, 0.05265332f);
    p = fmaf(a, p, -0.11643287f);
    p = fmaf(a, p,  0.19354346f);
    p = fmaf(a, p, -0.33262347f);
    p = fmaf(a, p,  0.99997726f);
    float r = t * p;
    if (ay > ax)  r = 1.57079632679f - r;
    if (x < 0.f)  r = 3.14159265359f - r;
    return (y < 0.f) ? -r : r;
}

__global__ __launch_bounds__(THREADS, 4)
void set_encoder_kernel(const float* __restrict__ player_locs,
                        const float* __restrict__ actor_locs,
                        const float* __restrict__ flags,
                        const int*   __restrict__ mask,
                        const float* __restrict__ W1,
                        const float* __restrict__ b1,
                        const float* __restrict__ W2,
                        const float* __restrict__ b2,
                        float*       __restrict__ out)
{
    __shared__ float  sW2[HID * OUTD];            // 32 KB
    __shared__ float  shh[WPB][HID][8];           // pooled hidden, 8 sets/chunk
    __shared__ float4 sf0[WPB][P];                // dx,dy,dist,angle
    __shared__ float2 sf1[WPB][P];                // teammate,keeper

    const int tid  = threadIdx.x;
    const int lane = tid & 31;
    const int wip  = tid >> 5;

    {   // stage W2 into shared once per block
        const float4* W2v  = (const float4*)W2;
        float4*       sW2v = (float4*)sW2;
        #pragma unroll
        for (int i = tid; i < HID * OUTD / 4; i += THREADS) sW2v[i] = W2v[i];
    }

    // W1 columns (lane, lane+32) in registers
    float w1a[INF_], w1b[INF_];
    #pragma unroll
    for (int i = 0; i < INF_; i++) {
        w1a[i] = W1[i * HID + lane];
        w1b[i] = W1[i * HID + lane + 32];
    }
    const float b1a = b1[lane];
    const float b1b = b1[lane + 32];
    const float2 bv0 = ((const float2*)b2)[lane];        // comps (2l, 2l+1)
    const float2 bv1 = ((const float2*)b2)[32 + lane];   // comps (64+2l, 64+2l+1)

    __syncthreads();

    // Balanced contiguous set ranges: warp w owns [512w/37, 512(w+1)/37)
    const int w  = blockIdx.x * WPB + wip;
    const int lo = (512 * w) / 37;
    const int hi = (512 * (w + 1)) / 37;

    for (int base = lo; base < hi; base += 8) {
        const int ns = min(8, hi - base);
        unsigned gmask = 0;   // bit s = set s non-empty (warp-uniform)

        // ---- per set: load, features, stage 1 (masked sum of relu(f@W1+b1)) ----
        for (int s = 0; s < ns; s++) {
            const int bset = base + s;
            int valid = 0;
            if (lane < P) {
                const int idx = bset * P + lane;
                valid = (mask[idx] != 0);
                if (valid) {
                    const float2 a  = ((const float2*)actor_locs)[bset];
                    const float2 pl = ((const float2*)player_locs)[idx];
                    const float2 fl = ((const float2*)flags)[idx];
                    const float dx = pl.x - a.x;
                    const float dy = pl.y - a.y;
                    const float d2 = fmaf(dx, dx, dy * dy);
                    const float dist = (d2 > 0.f) ? d2 * rsqrtf(d2) : 0.f;
                    const float ang  = fast_atan2(dy, dx);
                    sf0[wip][lane] = make_float4(dx, dy, dist, ang);
                    sf1[wip][lane] = fl;
                }
            }
            unsigned bal = __ballot_sync(0xffffffffu, valid);
            __syncwarp();
            const int cnt = __popc(bal);

            // two independent accumulation chains for ILP
            float ha0 = 0.f, hb0 = 0.f, ha1 = 0.f, hb1 = 0.f;
            while (bal) {
                const int p0 = __ffs(bal) - 1;
                bal &= bal - 1;
                {
                    const float4 f0 = sf0[wip][p0];   // broadcast LDS.128
                    const float2 f1 = sf1[wip][p0];   // broadcast LDS.64
                    float va = b1a, vb = b1b;
                    va = fmaf(f0.x, w1a[0], va);  vb = fmaf(f0.x, w1b[0], vb);
                    va = fmaf(f0.y, w1a[1], va);  vb = fmaf(f0.y, w1b[1], vb);
                    va = fmaf(f0.z, w1a[2], va);  vb = fmaf(f0.z, w1b[2], vb);
                    va = fmaf(f0.w, w1a[3], va);  vb = fmaf(f0.w, w1b[3], vb);
                    va = fmaf(f1.x, w1a[4], va);  vb = fmaf(f1.x, w1b[4], vb);
                    va = fmaf(f1.y, w1a[5], va);  vb = fmaf(f1.y, w1b[5], vb);
                    ha0 += fmaxf(va, 0.f);
                    hb0 += fmaxf(vb, 0.f);
                }
                if (bal) {     // warp-uniform
                    const int p1 = __ffs(bal) - 1;
                    bal &= bal - 1;
                    const float4 f0 = sf0[wip][p1];
                    const float2 f1 = sf1[wip][p1];
                    float va = b1a, vb = b1b;
                    va = fmaf(f0.x, w1a[0], va);  vb = fmaf(f0.x, w1b[0], vb);
                    va = fmaf(f0.y, w1a[1], va);  vb = fmaf(f0.y, w1b[1], vb);
                    va = fmaf(f0.z, w1a[2], va);  vb = fmaf(f0.z, w1b[2], vb);
                    va = fmaf(f0.w, w1a[3], va);  vb = fmaf(f0.w, w1b[3], vb);
                    va = fmaf(f1.x, w1a[4], va);  vb = fmaf(f1.x, w1b[4], vb);
                    va = fmaf(f1.y, w1a[5], va);  vb = fmaf(f1.y, w1b[5], vb);
                    ha1 += fmaxf(va, 0.f);
                    hb1 += fmaxf(vb, 0.f);
                }
            }

            const float rc = (cnt > 0) ? __fdividef(1.0f, (float)cnt) : 0.0f;
            gmask |= (cnt > 0) ? (1u << s) : 0u;
            shh[wip][lane     ][s] = (ha0 + ha1) * rc;
            shh[wip][lane + 32][s] = (hb0 + hb1) * rc;
            __syncwarp();   // sf0/sf1 reused next set; shh read in stage 2
        }

        // ---- stage 2: two passes, each computes 2 output comps/lane for 8 sets ----
        #pragma unroll
        for (int pass = 0; pass < 2; pass++) {
            const float2 bp = pass ? bv1 : bv0;
            unsigned long long acc[4][2];   // [set-pair][comp]
            #pragma unroll
            for (int p = 0; p < 4; p++) {
                const float g0 = ((gmask >> (2 * p))     & 1u) ? 1.f : 0.f;
                const float g1 = ((gmask >> (2 * p + 1)) & 1u) ? 1.f : 0.f;
                acc[p][0] = pack2(bp.x * g0, bp.x * g1);
                acc[p][1] = pack2(bp.y * g0, bp.y * g1);
            }

            const float2* w2r = (const float2*)sW2;   // [HID][OUTD/2]
            #pragma unroll
            for (int j = 0; j < HID; j++) {
                const float2 wv = w2r[j * (OUTD / 2) + pass * 32 + lane]; // LDS.64, conflict-free
                const ulonglong2* hp = (const ulonglong2*)&shh[wip][j][0];
                const ulonglong2 hA = hp[0];   // (s0,s1),(s2,s3) broadcast
                const ulonglong2 hB = hp[1];   // (s4,s5),(s6,s7) broadcast
                const unsigned long long wd0 = pack2(wv.x, wv.x);
                const unsigned long long wd1 = pack2(wv.y, wv.y);
                acc[0][0] = fma2(hA.x, wd0, acc[0][0]);
                acc[0][1] = fma2(hA.x, wd1, acc[0][1]);
                acc[1][0] = fma2(hA.y, wd0, acc[1][0]);
                acc[1][1] = fma2(hA.y, wd1, acc[1][1]);
                acc[2][0] = fma2(hB.x, wd0, acc[2][0]);
                acc[2][1] = fma2(hB.x, wd1, acc[2][1]);
                acc[3][0] = fma2(hB.y, wd0, acc[3][0]);
                acc[3][1] = fma2(hB.y, wd1, acc[3][1]);
            }

            // store this pass's half: out comps (pass*64 + 2l, +1) -> float2 idx pass*32+lane
            float2* ov = (float2*)out;
            #pragma unroll
            for (int p = 0; p < 4; p++) {
                float2 oa, ob;
                unpack2(acc[p][0], oa.x, ob.x);
                unpack2(acc[p][1], oa.y, ob.y);
                const int s0 = 2 * p, s1 = 2 * p + 1;
                if (s0 < ns)
                    ov[(size_t)(base + s0) * (OUTD / 2) + pass * 32 + lane] = oa;
                if (s1 < ns)
                    ov[(size_t)(base + s1) * (OUTD / 2) + pass * 32 + lane] = ob;
            }
        }
    }
}

extern "C" void kernel_launch(void* const* d_in, const int* in_sizes, int n_in,
                              void* d_out, int out_size)
{
    const float* player_locs = (const float*)d_in[0];
    const float* actor_locs  = (const float*)d_in[1];
    const float* flags       = (const float*)d_in[2];
    const int*   mask        = (const int*)  d_in[3];
    const float* W1          = (const float*)d_in[4];
    const float* b1          = (const float*)d_in[5];
    const float* W2          = (const float*)d_in[6];
    const float* b2          = (const float*)d_in[7];
    float*       out         = (float*)d_out;

    set_encoder_kernel<<<GRID, THREADS>>>(player_locs, actor_locs, flags, mask,
                                          W1, b1, W2, b2, out);
}

// round 14
// speedup vs baseline: 4.8102x; 4.8102x over previous
#include <cuda_runtime.h>
#include <math.h>

#define B_SETS 65536
#define P      22
#define INF_   6
#define HID    64
#define OUTD   128

#define WPB     8
#define THREADS (WPB * 32)
#define GRID    592                 // 148 SMs * 4 blocks/SM
#define S       4
#define NCHUNKS (B_SETS / S)        // 16384
#define NWARPS  (GRID * WPB)        // 4736
#define BASE_CHUNKS (NWARPS * 3)    // 14208 ; tail = 2176 = NWARPS*17/37

__device__ __forceinline__ unsigned long long pack2(float lo, float hi) {
    unsigned long long r;
    asm("mov.b64 %0, {%1,%2};" : "=l"(r) : "f"(lo), "f"(hi));
    return r;
}
__device__ __forceinline__ void unpack2(unsigned long long v, float& lo, float& hi) {
    asm("mov.b64 {%0,%1}, %2;" : "=f"(lo), "=f"(hi) : "l"(v));
}
__device__ __forceinline__ unsigned long long fma2(unsigned long long a,
                                                   unsigned long long b,
                                                   unsigned long long c) {
    unsigned long long d;
    asm("fma.rn.f32x2 %0, %1, %2, %3;" : "=l"(d) : "l"(a), "l"(b), "l"(c));
    return d;
}

// fast atan2: minimax deg-11 odd poly on [0,1], abs err ~1e-6 (output tol 1e-3)
__device__ __forceinline__ float fast_atan2(float y, float x) {
    const float ax = fabsf(x), ay = fabsf(y);
    const float mx = fmaxf(ax, ay), mn = fminf(ax, ay);
    float t = (mx > 0.f) ? __fdividef(mn, mx) : 0.f;
    const float a = t * t;
    float p = fmaf(a, -0.01172120f, 0.05265332f);
    p = fmaf(a, p, -0.11643287f);
    p = fmaf(a, p,  0.19354346f);
    p = fmaf(a, p, -0.33262347f);
    p = fmaf(a, p,  0.99997726f);
    float r = t * p;
    if (ay > ax)  r = 1.57079632679f - r;
    if (x < 0.f)  r = 3.14159265359f - r;
    return (y < 0.f) ? -r : r;
}

__global__ __launch_bounds__(THREADS, 4)
void set_encoder_kernel(const float* __restrict__ player_locs,
                        const float* __restrict__ actor_locs,
                        const float* __restrict__ flags,
                        const int*   __restrict__ mask,
                        const float* __restrict__ W1,
                        const float* __restrict__ b1,
                        const float* __restrict__ W2,
                        const float* __restrict__ b2,
                        float*       __restrict__ out)
{
    __shared__ float  sW2[HID * OUTD];            // 32 KB
    __shared__ float  shh[WPB][HID][S];           // pooled hidden per warp
    __shared__ float4 sf0[WPB][P];                // dx,dy,dist,angle
    __shared__ float2 sf1[WPB][P];                // teammate,keeper

    const int tid  = threadIdx.x;
    const int lane = tid & 31;
    const int wip  = tid >> 5;

    {   // stage W2 into shared once per block
        const float4* W2v  = (const float4*)W2;
        float4*       sW2v = (float4*)sW2;
        #pragma unroll
        for (int i = tid; i < HID * OUTD / 4; i += THREADS) sW2v[i] = W2v[i];
    }

    // W1 columns (lane, lane+32) in registers
    float w1a[INF_], w1b[INF_];
    #pragma unroll
    for (int i = 0; i < INF_; i++) {
        w1a[i] = W1[i * HID + lane];
        w1b[i] = W1[i * HID + lane + 32];
    }
    const float b1a = b1[lane];
    const float b1b = b1[lane + 32];
    float bv[4];
    {   const float4 t = ((const float4*)b2)[lane];
        bv[0] = t.x; bv[1] = t.y; bv[2] = t.z; bv[3] = t.w; }

    __syncthreads();

    const int w = blockIdx.x * WPB + wip;   // global warp id

    // Bresenham-balanced chunk list: 3 base chunks + possibly 1 tail chunk,
    // tail spread evenly across warps (hence across SMs).
    const int fw    = (w * 17) / 37;
    const int fw1   = ((w + 1) * 17) / 37;
    const int nmine = 3 + (fw1 - fw);

    for (int k = 0; k < nmine; k++) {
        const int chunk = (k < 3) ? (w + k * NWARPS) : (BASE_CHUNKS + fw);
        const int b0 = chunk * S;
        float gate[S];

        // ---- per set: load, features, stage 1 (masked sum of relu(f@W1+b1)) ----
        #pragma unroll 1
        for (int s = 0; s < S; s++) {
            const int bset = b0 + s;
            int valid = 0;
            if (lane < P) {
                const int idx = bset * P + lane;
                valid = (mask[idx] != 0);
                if (valid) {
                    const float2 a  = ((const float2*)actor_locs)[bset];
                    const float2 pl = ((const float2*)player_locs)[idx];
                    const float2 fl = ((const float2*)flags)[idx];
                    const float dx = pl.x - a.x;
                    const float dy = pl.y - a.y;
                    const float d2 = fmaf(dx, dx, dy * dy);
                    const float dist = (d2 > 0.f) ? d2 * rsqrtf(d2) : 0.f;
                    const float ang  = fast_atan2(dy, dx);
                    sf0[wip][lane] = make_float4(dx, dy, dist, ang);
                    sf1[wip][lane] = fl;
                }
            }
            unsigned bal = __ballot_sync(0xffffffffu, valid);  // orders STS above
            const int cnt = __popc(bal);

            float ha = 0.f, hb = 0.f;
            while (bal) {
                const int p = __ffs(bal) - 1;
                bal &= bal - 1;                       // warp-uniform
                const float4 f0 = sf0[wip][p];        // broadcast LDS.128
                const float2 f1 = sf1[wip][p];        // broadcast LDS.64
                float va = b1a, vb = b1b;
                va = fmaf(f0.x, w1a[0], va);  vb = fmaf(f0.x, w1b[0], vb);
                va = fmaf(f0.y, w1a[1], va);  vb = fmaf(f0.y, w1b[1], vb);
                va = fmaf(f0.z, w1a[2], va);  vb = fmaf(f0.z, w1b[2], vb);
                va = fmaf(f0.w, w1a[3], va);  vb = fmaf(f0.w, w1b[3], vb);
                va = fmaf(f1.x, w1a[4], va);  vb = fmaf(f1.x, w1b[4], vb);
                va = fmaf(f1.y, w1a[5], va);  vb = fmaf(f1.y, w1b[5], vb);
                ha += fmaxf(va, 0.f);
                hb += fmaxf(vb, 0.f);
            }

            const float rc = (cnt > 0) ? __fdividef(1.0f, (float)cnt) : 0.0f;
            gate[s] = (cnt > 0) ? 1.0f : 0.0f;
            shh[wip][lane     ][s] = ha * rc;
            shh[wip][lane + 32][s] = hb * rc;
            __syncwarp();   // protect sf0/sf1 overwrite next set; shh before stage 2
        }

        // ---- stage 2: out[s] = h[s] @ W2 + gate[s]*b2, 4 sets at a time ----
        unsigned long long acc01[4], acc23[4];
        #pragma unroll
        for (int c = 0; c < 4; c++) {
            acc01[c] = pack2(bv[c] * gate[0], bv[c] * gate[1]);
            acc23[c] = pack2(bv[c] * gate[2], bv[c] * gate[3]);
        }

        const float4* w2r  = (const float4*)sW2;
        const float4* hrow = (const float4*)&shh[wip][0][0];
        #pragma unroll
        for (int j = 0; j < HID; j++) {
            const float4 wv = w2r[j * (OUTD / 4) + lane];  // per-lane LDS.128
            const float4 hv = hrow[j];                     // broadcast: h_j, 4 sets
            const unsigned long long h01 = pack2(hv.x, hv.y);
            const unsigned long long h23 = pack2(hv.z, hv.w);
            const unsigned long long wd0 = pack2(wv.x, wv.x);
            const unsigned long long wd1 = pack2(wv.y, wv.y);
            const unsigned long long wd2 = pack2(wv.z, wv.z);
            const unsigned long long wd3 = pack2(wv.w, wv.w);
            acc01[0] = fma2(h01, wd0, acc01[0]);  acc23[0] = fma2(h23, wd0, acc23[0]);
            acc01[1] = fma2(h01, wd1, acc01[1]);  acc23[1] = fma2(h23, wd1, acc23[1]);
            acc01[2] = fma2(h01, wd2, acc01[2]);  acc23[2] = fma2(h23, wd2, acc23[2]);
            acc01[3] = fma2(h01, wd3, acc01[3]);  acc23[3] = fma2(h23, wd3, acc23[3]);
        }

        float4 o0, o1, o2, o3;
        unpack2(acc01[0], o0.x, o1.x);  unpack2(acc23[0], o2.x, o3.x);
        unpack2(acc01[1], o0.y, o1.y);  unpack2(acc23[1], o2.y, o3.y);
        unpack2(acc01[2], o0.z, o1.z);  unpack2(acc23[2], o2.z, o3.z);
        unpack2(acc01[3], o0.w, o1.w);  unpack2(acc23[3], o2.w, o3.w);
        float4* ov = (float4*)out;
        ov[(b0 + 0) * (OUTD / 4) + lane] = o0;
        ov[(b0 + 1) * (OUTD / 4) + lane] = o1;
        ov[(b0 + 2) * (OUTD / 4) + lane] = o2;
        ov[(b0 + 3) * (OUTD / 4) + lane] = o3;
    }
}

extern "C" void kernel_launch(void* const* d_in, const int* in_sizes, int n_in,
                              void* d_out, int out_size)
{
    const float* player_locs = (const float*)d_in[0];
    const float* actor_locs  = (const float*)d_in[1];
    const float* flags       = (const float*)d_in[2];
    const int*   mask        = (const int*)  d_in[3];
    const float* W1          = (const float*)d_in[4];
    const float* b1          = (const float*)d_in[5];
    const float* W2          = (const float*)d_in[6];
    const float* b2          = (const float*)d_in[7];
    float*       out         = (float*)d_out;

    set_encoder_kernel<<<GRID, THREADS>>>(player_locs, actor_locs, flags, mask,
                                          W1, b1, W2, b2, out);
}